// round 15
// baseline (speedup 1.0000x reference)
#include <cuda_runtime.h>
#include <cuda_bf16.h>
#include <stdint.h>
#include <math.h>
#include <float.h>

#define NF 128
#define NB 64
#define NODES1 131072
#define EMAX 2097152
#define CAP 64

// ---------------- scratch (static device globals; no allocation) ----------------
__device__ float g_h[NODES1 * NF];        // ping (pooled h)
__device__ float g_h2[NODES1 * NF];       // pong (gemm output)
__device__ float g_mean[NODES1 * NF];     // aggregated means
__device__ int   g_slotA[NODES1 * CAP];   // adjacency slots (ping)
__device__ int   g_slotB[NODES1 * CAP];   // adjacency slots (pong)
__device__ int   g_degA[NODES1];
__device__ int   g_degB[NODES1];
__device__ int   g_kept[NODES1];
__device__ int   g_newidx[NODES1];
__device__ float g_score[NODES1];
__device__ float g_z[NB * 256];
__device__ __nv_bfloat16 g_wthi[3 * 128 * 256];  // transposed [N=128,K=256] hi parts
__device__ __nv_bfloat16 g_wtlo[3 * 128 * 256];  // lo parts

// ---------------- mma helpers ----------------
__device__ __forceinline__ uint32_t smem_to_u32(const void* p) {
    uint32_t a;
    asm("{ .reg .u64 t; cvta.to.shared.u64 t, %1; cvt.u32.u64 %0, t; }" : "=r"(a) : "l"(p));
    return a;
}
__device__ __forceinline__ void ldsm_x4(uint32_t r[4], uint32_t addr) {
    asm volatile("ldmatrix.sync.aligned.m8n8.x4.shared.b16 {%0,%1,%2,%3}, [%4];"
                 : "=r"(r[0]), "=r"(r[1]), "=r"(r[2]), "=r"(r[3]) : "r"(addr));
}
__device__ __forceinline__ void mma_bf16(float* c, const uint32_t* a, const uint32_t* b) {
    asm volatile("mma.sync.aligned.m16n8k16.row.col.f32.bf16.bf16.f32 "
                 "{%0,%1,%2,%3}, {%4,%5,%6,%7}, {%8,%9}, {%0,%1,%2,%3};"
                 : "+f"(c[0]), "+f"(c[1]), "+f"(c[2]), "+f"(c[3])
                 : "r"(a[0]), "r"(a[1]), "r"(a[2]), "r"(a[3]), "r"(b[0]), "r"(b[1]));
}

// SMEM tile geometry: [128 rows][256 k] bf16, padded pitch 264 bf16 (528 B)
#define PITCHB   528
#define OFF_AHI  0
#define OFF_ALO  67584
#define OFF_W    135168
#define OFF_BIAS 202752
#define OFF_PW   203264
#define OFF_SC   203776
#define OFF_INV  204288
#define GSMEM    204304

// ---------------- setup: zero layer-1 state + z + weight transpose/split (fused) ----------------
__global__ void k_setup(const float* __restrict__ w1l, const float* __restrict__ w1r,
                        const float* __restrict__ w2l, const float* __restrict__ w2r,
                        const float* __restrict__ w3l, const float* __restrict__ w3r,
                        __nv_bfloat16* __restrict__ whi, __nv_bfloat16* __restrict__ wlo) {
    int i = blockIdx.x * blockDim.x + threadIdx.x;   // 512*256 = 131072
    g_degA[i] = 0;
    if (i < NB * 256) g_z[i] = 0.f;
    if (i < 98304) {
        int seg = i >> 15, local = i & 32767;
        int n = local >> 8, k = local & 255;
        const float* wl = (seg == 0) ? w1l : (seg == 1) ? w2l : w3l;
        const float* wr = (seg == 0) ? w1r : (seg == 1) ? w2r : w3r;
        float w = (k < 128) ? wl[k * 128 + n] : wr[(k - 128) * 128 + n];
        __nv_bfloat16 hi = __float2bfloat16_rn(w);
        __nv_bfloat16 lo = __float2bfloat16_rn(w - __bfloat162float(hi));
        whi[i] = hi;
        wlo[i] = lo;
    }
}

// ---------------- layer-1 adjacency build: 4 independent atomic chains per thread ----------------
__global__ void k_slot1(const int* __restrict__ src, const int* __restrict__ dst,
                        int* __restrict__ curs, int* __restrict__ slot) {
    int t = blockIdx.x * blockDim.x + threadIdx.x;   // EMAX/4 threads
    int e = t * 4;
    int4 d4 = *(const int4*)(dst + e);
    int4 s4 = *(const int4*)(src + e);
    int p0 = atomicAdd(&curs[d4.x], 1);
    int p1 = atomicAdd(&curs[d4.y], 1);
    int p2 = atomicAdd(&curs[d4.z], 1);
    int p3 = atomicAdd(&curs[d4.w], 1);
    slot[(size_t)d4.x * CAP + p0] = s4.x;
    slot[(size_t)d4.y * CAP + p1] = s4.y;
    slot[(size_t)d4.z * CAP + p2] = s4.z;
    slot[(size_t)d4.w * CAP + p3] = s4.w;
}

// ---------------- neighbor mean aggregation: one warp per node, 8-wide MLP ----------------
__global__ void k_aggregate(const float* __restrict__ x, const int* __restrict__ slot,
                            const int* __restrict__ deg, float* __restrict__ mb) {
    int node = blockIdx.x * 8 + (threadIdx.x >> 5);
    int lane = threadIdx.x & 31;
    const int* row = slot + (size_t)node * CAP;
    int d = deg[node];
    float ax = 0.f, ay = 0.f, az = 0.f, aw = 0.f;
    int j = 0;
    for (; j + 8 <= d; j += 8) {
        float4 v[8];
        #pragma unroll
        for (int q = 0; q < 8; q++) {
            int s = row[j + q];
            v[q] = *(const float4*)(x + (size_t)s * NF + lane * 4);
        }
        #pragma unroll
        for (int q = 0; q < 8; q++) {
            ax += v[q].x; ay += v[q].y; az += v[q].z; aw += v[q].w;
        }
    }
    for (; j + 4 <= d; j += 4) {
        float4 v[4];
        #pragma unroll
        for (int q = 0; q < 4; q++) {
            int s = row[j + q];
            v[q] = *(const float4*)(x + (size_t)s * NF + lane * 4);
        }
        #pragma unroll
        for (int q = 0; q < 4; q++) {
            ax += v[q].x; ay += v[q].y; az += v[q].z; aw += v[q].w;
        }
    }
    for (; j < d; j++) {
        int s = row[j];
        float4 v = *(const float4*)(x + (size_t)s * NF + lane * 4);
        ax += v.x; ay += v.y; az += v.z; aw += v.w;
    }
    float inv = 1.f / (float)(d > 0 ? d : 1);
    float4 o; o.x = ax * inv; o.y = ay * inv; o.z = az * inv; o.w = aw * inv;
    *(float4*)(mb + (size_t)node * NF + lane * 4) = o;
}

// ---------------- warp-mma GEMM: h = relu([mean|x] @ Wt^T + b), fused score ----------------
__device__ __forceinline__ void gemm_pass(uint32_t aBase, uint32_t wBase,
                                          int wm, int wn, int lane, float cc[16][4]) {
    int arow = wm + (lane & 15);
    int acol = (lane >> 4) << 3;
    uint32_t aaddr = aBase + (uint32_t)arow * PITCHB + (uint32_t)acol * 2;
    int brow = (lane & 7) + ((lane >> 4) << 3);
    int bcol = ((lane >> 3) & 1) << 3;
    uint32_t baddr = wBase + (uint32_t)(wn + brow) * PITCHB + (uint32_t)bcol * 2;
    #pragma unroll
    for (int ks = 0; ks < 16; ks++) {
        uint32_t a0[4], a1[4], b[4][4];
        ldsm_x4(a0, aaddr + ks * 32);
        ldsm_x4(a1, aaddr + 16 * PITCHB + ks * 32);
        #pragma unroll
        for (int ng = 0; ng < 4; ng++)
            ldsm_x4(b[ng], baddr + ng * 16 * PITCHB + ks * 32);
        #pragma unroll
        for (int nt = 0; nt < 8; nt++) {
            mma_bf16(cc[nt],     a0, &b[nt >> 1][(nt & 1) * 2]);
            mma_bf16(cc[8 + nt], a1, &b[nt >> 1][(nt & 1) * 2]);
        }
    }
}

__global__ void __launch_bounds__(256) k_gemm_tc(
    const float* __restrict__ A, const float* __restrict__ X,
    const __nv_bfloat16* __restrict__ wthi, const __nv_bfloat16* __restrict__ wtlo,
    const float* __restrict__ bias, const float* __restrict__ pw,
    float* __restrict__ out, float* __restrict__ score) {
    extern __shared__ char smem[];
    uint32_t sb = smem_to_u32(smem);
    int tid = threadIdx.x, wid = tid >> 5, lane = tid & 31;
    int r0 = blockIdx.x * 128;

    float* sbias = (float*)(smem + OFF_BIAS);
    float* spw   = (float*)(smem + OFF_PW);
    float* ssc   = (float*)(smem + OFF_SC);
    if (tid < 128) {
        sbias[tid] = bias[tid];
        spw[tid] = pw[tid];
        ssc[tid] = 0.f;
    }
    __syncthreads();
    if (tid == 0) {
        float s = 0.f;
        for (int i = 0; i < 128; i++) s += spw[i] * spw[i];
        *(float*)(smem + OFF_INV) = rsqrtf(s);
    }

    for (int c = tid; c < 4096; c += 256) {
        int row = c >> 5, col4 = (c & 31) << 2;
        float4 v = *(const float4*)(A + (size_t)(r0 + row) * 128 + col4);
        float4 u = *(const float4*)(X + (size_t)(r0 + row) * 128 + col4);
        #pragma unroll
        for (int half = 0; half < 2; half++) {
            float4 w = half ? u : v;
            __nv_bfloat16 hx = __float2bfloat16_rn(w.x), hy = __float2bfloat16_rn(w.y);
            __nv_bfloat16 hz = __float2bfloat16_rn(w.z), hw = __float2bfloat16_rn(w.w);
            __nv_bfloat16 lx = __float2bfloat16_rn(w.x - __bfloat162float(hx));
            __nv_bfloat16 ly = __float2bfloat16_rn(w.y - __bfloat162float(hy));
            __nv_bfloat16 lz = __float2bfloat16_rn(w.z - __bfloat162float(hz));
            __nv_bfloat16 lw = __float2bfloat16_rn(w.w - __bfloat162float(hw));
            __nv_bfloat162 h01 = __halves2bfloat162(hx, hy), h23 = __halves2bfloat162(hz, hw);
            __nv_bfloat162 l01 = __halves2bfloat162(lx, ly), l23 = __halves2bfloat162(lz, lw);
            uint32_t off = (uint32_t)row * PITCHB + (uint32_t)(half * 128 + col4) * 2;
            uint2 hv; hv.x = *(uint32_t*)&h01; hv.y = *(uint32_t*)&h23;
            uint2 lv; lv.x = *(uint32_t*)&l01; lv.y = *(uint32_t*)&l23;
            *(uint2*)(smem + OFF_AHI + off) = hv;
            *(uint2*)(smem + OFF_ALO + off) = lv;
        }
    }
    for (int c = tid; c < 4096; c += 256) {
        int n = c >> 5, k8 = (c & 31) << 3;
        uint4 raw = *(const uint4*)(wthi + (size_t)n * 256 + k8);
        *(uint4*)(smem + OFF_W + (uint32_t)n * PITCHB + (uint32_t)k8 * 2) = raw;
    }
    __syncthreads();

    int wm = (wid & 3) * 32, wn = (wid >> 2) * 64;
    float cc[16][4];
    #pragma unroll
    for (int i = 0; i < 16; i++)
        #pragma unroll
        for (int j = 0; j < 4; j++) cc[i][j] = 0.f;

    gemm_pass(sb + OFF_AHI, sb + OFF_W, wm, wn, lane, cc);   // A_hi * W_hi
    gemm_pass(sb + OFF_ALO, sb + OFF_W, wm, wn, lane, cc);   // A_lo * W_hi
    __syncthreads();
    for (int c = tid; c < 4096; c += 256) {                  // swap in W_lo
        int n = c >> 5, k8 = (c & 31) << 3;
        uint4 raw = *(const uint4*)(wtlo + (size_t)n * 256 + k8);
        *(uint4*)(smem + OFF_W + (uint32_t)n * PITCHB + (uint32_t)k8 * 2) = raw;
    }
    __syncthreads();
    gemm_pass(sb + OFF_AHI, sb + OFF_W, wm, wn, lane, cc);   // A_hi * W_lo

    int g = lane >> 2, tig = lane & 3;
    float p[4] = {0.f, 0.f, 0.f, 0.f};
    #pragma unroll
    for (int mt = 0; mt < 2; mt++) {
        #pragma unroll
        for (int nt = 0; nt < 8; nt++) {
            float* cf = cc[mt * 8 + nt];
            int col0 = wn + nt * 8 + tig * 2;
            float pw0 = spw[col0], pw1 = spw[col0 + 1];
            float b0 = sbias[col0], b1 = sbias[col0 + 1];
            float o0 = fmaxf(cf[0] + b0, 0.f), o1 = fmaxf(cf[1] + b1, 0.f);
            float o2 = fmaxf(cf[2] + b0, 0.f), o3 = fmaxf(cf[3] + b1, 0.f);
            int rowA = r0 + wm + mt * 16 + g;
            float2 s0; s0.x = o0; s0.y = o1;
            float2 s1; s1.x = o2; s1.y = o3;
            *(float2*)(out + (size_t)rowA * 128 + col0) = s0;
            *(float2*)(out + (size_t)(rowA + 8) * 128 + col0) = s1;
            p[mt * 2 + 0] += o0 * pw0 + o1 * pw1;
            p[mt * 2 + 1] += o2 * pw0 + o3 * pw1;
        }
    }
    #pragma unroll
    for (int off = 1; off <= 2; off <<= 1) {
        #pragma unroll
        for (int i = 0; i < 4; i++) p[i] += __shfl_xor_sync(0xffffffffu, p[i], off);
    }
    if (tig == 0) {
        atomicAdd(&ssc[wm + g], p[0]);
        atomicAdd(&ssc[wm + 8 + g], p[1]);
        atomicAdd(&ssc[wm + 16 + g], p[2]);
        atomicAdd(&ssc[wm + 24 + g], p[3]);
    }
    __syncthreads();
    if (tid < 128) {
        float invn = *(const float*)(smem + OFF_INV);
        score[r0 + tid] = tanhf(ssc[tid] * invn);
    }
}

// ---------------- per-graph top-k pool + fused readout ----------------
__global__ void k_pool(const float* __restrict__ h, const float* __restrict__ score,
                       float* __restrict__ hout, int* __restrict__ kept,
                       int* __restrict__ newidx, float* __restrict__ z,
                       int n_per, int k) {
    __shared__ unsigned long long s_key[2048];
    __shared__ float red[32][128];
    int g = blockIdx.x;
    int tid = threadIdx.x;
    int bd = blockDim.x;
    int base = g * n_per;
    for (int i = tid; i < n_per; i += bd) {
        float s = score[base + i];
        unsigned u = __float_as_uint(s);
        unsigned au = (u & 0x80000000u) ? ~u : (u | 0x80000000u);
        unsigned du = ~au;
        s_key[i] = ((unsigned long long)du << 32) | (unsigned)i;
        kept[base + i] = 0;
    }
    for (int size = 2; size <= n_per; size <<= 1) {
        for (int stride = size >> 1; stride > 0; stride >>= 1) {
            __syncthreads();
            int half = n_per >> 1;
            for (int t = tid; t < half; t += bd) {
                int i = 2 * t - (t & (stride - 1));
                int j = i + stride;
                unsigned long long a = s_key[i], c = s_key[j];
                bool up = ((i & size) == 0);
                if ((a > c) == up) { s_key[i] = c; s_key[j] = a; }
            }
        }
    }
    __syncthreads();
    for (int t = tid; t < k; t += bd) {
        int li = (int)(s_key[t] & 0xffffffffull);
        kept[base + li] = 1;
        newidx[base + li] = g * k + t;
    }
    // gather + gate + accumulate per-graph max/sum (fused readout)
    int w = tid >> 5, lane = tid & 31;
    float mx0 = -FLT_MAX, mx1 = -FLT_MAX, mx2 = -FLT_MAX, mx3 = -FLT_MAX;
    float sm0 = 0.f, sm1 = 0.f, sm2 = 0.f, sm3 = 0.f;
    for (int t = w; t < k; t += 32) {
        int li = (int)(s_key[t] & 0xffffffffull);
        int v = base + li;
        float sc = score[v];
        float4 val = *(const float4*)(h + (size_t)v * NF + lane * 4);
        float4 o; o.x = val.x * sc; o.y = val.y * sc; o.z = val.z * sc; o.w = val.w * sc;
        *(float4*)(hout + (size_t)(g * k + t) * NF + lane * 4) = o;
        mx0 = fmaxf(mx0, o.x); mx1 = fmaxf(mx1, o.y);
        mx2 = fmaxf(mx2, o.z); mx3 = fmaxf(mx3, o.w);
        sm0 += o.x; sm1 += o.y; sm2 += o.z; sm3 += o.w;
    }
    red[w][lane * 4 + 0] = mx0; red[w][lane * 4 + 1] = mx1;
    red[w][lane * 4 + 2] = mx2; red[w][lane * 4 + 3] = mx3;
    __syncthreads();
    if (tid < 128) {
        float m = red[0][tid];
        #pragma unroll
        for (int j = 1; j < 32; j++) m = fmaxf(m, red[j][tid]);
        z[g * 256 + tid] += m;
    }
    __syncthreads();
    red[w][lane * 4 + 0] = sm0; red[w][lane * 4 + 1] = sm1;
    red[w][lane * 4 + 2] = sm2; red[w][lane * 4 + 3] = sm3;
    __syncthreads();
    if (tid < 128) {
        float s = 0.f;
        #pragma unroll
        for (int j = 0; j < 32; j++) s += red[j][tid];
        z[g * 256 + 128 + tid] += s / (float)k;
    }
}

// ---------------- fused edge-compact + adjacency build (atomic-free) ----------------
__global__ void k_compact_slot(const int* __restrict__ oslot, const int* __restrict__ odeg,
                               const int* __restrict__ kept, const int* __restrict__ newidx,
                               int* __restrict__ nslot, int* __restrict__ ndeg, int n_old) {
    int node = blockIdx.x * 8 + (threadIdx.x >> 5);
    if (node >= n_old) return;
    int lane = threadIdx.x & 31;
    if (!kept[node]) return;                  // warp-uniform
    int nid = newidx[node];
    int d = odeg[node];
    const int* row = oslot + (size_t)node * CAP;
    int* nrow = nslot + (size_t)nid * CAP;
    int total = 0;
    #pragma unroll
    for (int half = 0; half < CAP; half += 32) {
        int j = half + lane;
        bool keep = false;
        int ns = 0;
        if (j < d) {
            int s = row[j];
            if (kept[s]) { keep = true; ns = newidx[s]; }
        }
        unsigned m = __ballot_sync(0xffffffffu, keep);
        if (keep) nrow[total + __popc(m & ((1u << lane) - 1u))] = ns;
        total += __popc(m);
        if (d <= half + 32) break;
    }
    if (lane == 0) ndeg[nid] = total;
}

// ---------------- final MLP + log_softmax ----------------
__global__ void k_mlp(const float* __restrict__ z,
                      const float* __restrict__ w1, const float* __restrict__ b1,
                      const float* __restrict__ w2, const float* __restrict__ b2,
                      const float* __restrict__ w3, const float* __restrict__ b3,
                      float* __restrict__ out) {
    __shared__ float zin[256];
    __shared__ float h1[128];
    __shared__ float h2[64];
    __shared__ float z2[2];
    int g = blockIdx.x, tid = threadIdx.x;
    zin[tid] = z[g * 256 + tid];
    zin[tid + 128] = z[g * 256 + 128 + tid];
    __syncthreads();
    float a = b1[tid];
    for (int k2 = 0; k2 < 256; k2++) a += zin[k2] * w1[k2 * 128 + tid];
    h1[tid] = fmaxf(a, 0.f);
    __syncthreads();
    if (tid < 64) {
        float a2 = b2[tid];
        for (int k2 = 0; k2 < 128; k2++) a2 += h1[k2] * w2[k2 * 64 + tid];
        h2[tid] = fmaxf(a2, 0.f);
    }
    __syncthreads();
    if (tid < 2) {
        float a3 = b3[tid];
        for (int k2 = 0; k2 < 64; k2++) a3 += h2[k2] * w3[k2 * 2 + tid];
        z2[tid] = a3;
    }
    __syncthreads();
    if (tid < 2) {
        float m = fmaxf(z2[0], z2[1]);
        float lse = m + logf(expf(z2[0] - m) + expf(z2[1] - m));
        out[g * 2 + tid] = z2[tid] - lse;
    }
}

// ---------------- host ----------------
extern "C" void kernel_launch(void* const* d_in, const int* in_sizes, int n_in,
                              void* d_out, int out_size) {
    const float* x   = (const float*)d_in[0];
    const int*   src = (const int*)d_in[1];
    const int*   dst = (const int*)d_in[2];
    const float* w1l = (const float*)d_in[3];
    const float* b1  = (const float*)d_in[4];
    const float* w1r = (const float*)d_in[5];
    const float* pw1 = (const float*)d_in[6];
    const float* w2l = (const float*)d_in[7];
    const float* b2  = (const float*)d_in[8];
    const float* w2r = (const float*)d_in[9];
    const float* pw2 = (const float*)d_in[10];
    const float* w3l = (const float*)d_in[11];
    const float* b3  = (const float*)d_in[12];
    const float* w3r = (const float*)d_in[13];
    const float* pw3 = (const float*)d_in[14];
    const float* l1w = (const float*)d_in[15];
    const float* l1b = (const float*)d_in[16];
    const float* l2w = (const float*)d_in[17];
    const float* l2b = (const float*)d_in[18];
    const float* l3w = (const float*)d_in[19];
    const float* l3b = (const float*)d_in[20];
    float* out = (float*)d_out;

    float *p_h, *p_h2, *p_mean, *p_score, *p_z;
    int *p_slotA, *p_slotB, *p_degA, *p_degB, *p_kept, *p_newidx;
    __nv_bfloat16 *p_wthi, *p_wtlo;
    cudaGetSymbolAddress((void**)&p_h, g_h);
    cudaGetSymbolAddress((void**)&p_h2, g_h2);
    cudaGetSymbolAddress((void**)&p_mean, g_mean);
    cudaGetSymbolAddress((void**)&p_score, g_score);
    cudaGetSymbolAddress((void**)&p_z, g_z);
    cudaGetSymbolAddress((void**)&p_slotA, g_slotA);
    cudaGetSymbolAddress((void**)&p_slotB, g_slotB);
    cudaGetSymbolAddress((void**)&p_degA, g_degA);
    cudaGetSymbolAddress((void**)&p_degB, g_degB);
    cudaGetSymbolAddress((void**)&p_kept, g_kept);
    cudaGetSymbolAddress((void**)&p_newidx, g_newidx);
    cudaGetSymbolAddress((void**)&p_wthi, g_wthi);
    cudaGetSymbolAddress((void**)&p_wtlo, g_wtlo);

    cudaFuncSetAttribute(k_gemm_tc, cudaFuncAttributeMaxDynamicSharedMemorySize, GSMEM);

    // ===== layer 1 (launch #4 = k_gemm_tc -> ncu sample) =====
    k_setup<<<512, 256>>>(w1l, w1r, w2l, w2r, w3l, w3r, p_wthi, p_wtlo);
    k_slot1<<<EMAX / 1024, 256>>>(src, dst, p_degA, p_slotA);
    k_aggregate<<<131072 / 8, 256>>>(x, p_slotA, p_degA, p_mean);
    k_gemm_tc<<<131072 / 128, 256, GSMEM>>>(p_mean, x, p_wthi, p_wtlo, b1, pw1, p_h2, p_score);
    k_pool<<<64, 1024>>>(p_h2, p_score, p_h, p_kept, p_newidx, p_z, 2048, 1024);
    k_compact_slot<<<131072 / 8, 256>>>(p_slotA, p_degA, p_kept, p_newidx,
                                        p_slotB, p_degB, 131072);

    // ===== layer 2 =====
    k_aggregate<<<65536 / 8, 256>>>(p_h, p_slotB, p_degB, p_mean);
    k_gemm_tc<<<65536 / 128, 256, GSMEM>>>(p_mean, p_h, p_wthi + 32768, p_wtlo + 32768, b2, pw2, p_h2, p_score);
    k_pool<<<64, 1024>>>(p_h2, p_score, p_h, p_kept, p_newidx, p_z, 1024, 512);
    k_compact_slot<<<65536 / 8, 256>>>(p_slotB, p_degB, p_kept, p_newidx,
                                       p_slotA, p_degA, 65536);

    // ===== layer 3 =====
    k_aggregate<<<32768 / 8, 256>>>(p_h, p_slotA, p_degA, p_mean);
    k_gemm_tc<<<32768 / 128, 256, GSMEM>>>(p_mean, p_h, p_wthi + 65536, p_wtlo + 65536, b3, pw3, p_h2, p_score);
    k_pool<<<64, 1024>>>(p_h2, p_score, p_h, p_kept, p_newidx, p_z, 512, 256);

    // ===== head =====
    k_mlp<<<64, 128>>>(p_z, l1w, l1b, l2w, l2b, l3w, l3b, out);
}

// round 17
// speedup vs baseline: 1.0664x; 1.0664x over previous
#include <cuda_runtime.h>
#include <cuda_bf16.h>
#include <stdint.h>
#include <math.h>
#include <float.h>

#define NF 128
#define NB 64
#define NODES1 131072
#define EMAX 2097152
#define CAP 64

// ---------------- scratch (static device globals; no allocation) ----------------
__device__ float g_h[NODES1 * NF];        // ping (pooled h)
__device__ float g_h2[NODES1 * NF];       // pong (gemm output)
__device__ float g_mean[NODES1 * NF];     // aggregated means
__device__ int   g_slotA[NODES1 * CAP];   // adjacency slots (ping)
__device__ int   g_slotB[NODES1 * CAP];   // adjacency slots (pong)
__device__ int   g_degA[NODES1];
__device__ int   g_degB[NODES1];
__device__ int   g_kept[NODES1];
__device__ int   g_newidx[NODES1];
__device__ float g_score[NODES1];
__device__ float g_z[NB * 256];
__device__ __nv_bfloat16 g_wthi[3 * 128 * 256];  // transposed [N=128,K=256] hi parts
__device__ __nv_bfloat16 g_wtlo[3 * 128 * 256];  // lo parts

// ---------------- mma helpers ----------------
__device__ __forceinline__ uint32_t smem_to_u32(const void* p) {
    uint32_t a;
    asm("{ .reg .u64 t; cvta.to.shared.u64 t, %1; cvt.u32.u64 %0, t; }" : "=r"(a) : "l"(p));
    return a;
}
__device__ __forceinline__ void ldsm_x4(uint32_t r[4], uint32_t addr) {
    asm volatile("ldmatrix.sync.aligned.m8n8.x4.shared.b16 {%0,%1,%2,%3}, [%4];"
                 : "=r"(r[0]), "=r"(r[1]), "=r"(r[2]), "=r"(r[3]) : "r"(addr));
}
__device__ __forceinline__ void mma_bf16(float* c, const uint32_t* a, const uint32_t* b) {
    asm volatile("mma.sync.aligned.m16n8k16.row.col.f32.bf16.bf16.f32 "
                 "{%0,%1,%2,%3}, {%4,%5,%6,%7}, {%8,%9}, {%0,%1,%2,%3};"
                 : "+f"(c[0]), "+f"(c[1]), "+f"(c[2]), "+f"(c[3])
                 : "r"(a[0]), "r"(a[1]), "r"(a[2]), "r"(a[3]), "r"(b[0]), "r"(b[1]));
}

// SMEM tile geometry: [128 rows][256 k] bf16, padded pitch 264 bf16 (528 B)
#define PITCHB   528
#define OFF_AHI  0
#define OFF_ALO  67584
#define OFF_W    135168
#define OFF_BIAS 202752
#define OFF_PW   203264
#define OFF_SC   203776
#define OFF_INV  204288
#define GSMEM    204304

// ---------------- setup: zero layer-1 state + z + weight transpose/split (fused) ----------------
__global__ void k_setup(const float* __restrict__ w1l, const float* __restrict__ w1r,
                        const float* __restrict__ w2l, const float* __restrict__ w2r,
                        const float* __restrict__ w3l, const float* __restrict__ w3r,
                        __nv_bfloat16* __restrict__ whi, __nv_bfloat16* __restrict__ wlo) {
    int i = blockIdx.x * blockDim.x + threadIdx.x;   // 512*256 = 131072
    g_degA[i] = 0;
    if (i < NB * 256) g_z[i] = 0.f;
    if (i < 98304) {
        int seg = i >> 15, local = i & 32767;
        int n = local >> 8, k = local & 255;
        const float* wl = (seg == 0) ? w1l : (seg == 1) ? w2l : w3l;
        const float* wr = (seg == 0) ? w1r : (seg == 1) ? w2r : w3r;
        float w = (k < 128) ? wl[k * 128 + n] : wr[(k - 128) * 128 + n];
        __nv_bfloat16 hi = __float2bfloat16_rn(w);
        __nv_bfloat16 lo = __float2bfloat16_rn(w - __bfloat162float(hi));
        whi[i] = hi;
        wlo[i] = lo;
    }
}

// ---------------- layer-1 adjacency build: single atomic pass into slots ----------------
__global__ void k_slot1(const int* __restrict__ src, const int* __restrict__ dst,
                        int* __restrict__ curs, int* __restrict__ slot) {
    int e = blockIdx.x * blockDim.x + threadIdx.x;   // grid covers EMAX exactly
    int d = dst[e];
    int p = atomicAdd(&curs[d], 1);
    slot[(size_t)d * CAP + p] = src[e];
}

// ---------------- neighbor mean aggregation: one warp per node ----------------
__global__ void k_aggregate(const float* __restrict__ x, const int* __restrict__ slot,
                            const int* __restrict__ deg, float* __restrict__ mb) {
    int node = blockIdx.x * 8 + (threadIdx.x >> 5);
    int lane = threadIdx.x & 31;
    const int* row = slot + (size_t)node * CAP;
    int d = deg[node];
    float ax = 0.f, ay = 0.f, az = 0.f, aw = 0.f;
    int j = 0;
    for (; j + 4 <= d; j += 4) {
        int s0 = row[j], s1 = row[j + 1], s2 = row[j + 2], s3 = row[j + 3];
        float4 v0 = *(const float4*)(x + (size_t)s0 * NF + lane * 4);
        float4 v1 = *(const float4*)(x + (size_t)s1 * NF + lane * 4);
        float4 v2 = *(const float4*)(x + (size_t)s2 * NF + lane * 4);
        float4 v3 = *(const float4*)(x + (size_t)s3 * NF + lane * 4);
        ax += v0.x + v1.x + v2.x + v3.x;
        ay += v0.y + v1.y + v2.y + v3.y;
        az += v0.z + v1.z + v2.z + v3.z;
        aw += v0.w + v1.w + v2.w + v3.w;
    }
    for (; j < d; j++) {
        int s = row[j];
        float4 v = *(const float4*)(x + (size_t)s * NF + lane * 4);
        ax += v.x; ay += v.y; az += v.z; aw += v.w;
    }
    float inv = 1.f / (float)(d > 0 ? d : 1);
    float4 o; o.x = ax * inv; o.y = ay * inv; o.z = az * inv; o.w = aw * inv;
    *(float4*)(mb + (size_t)node * NF + lane * 4) = o;
}

// ---------------- warp-mma GEMM: h = relu([mean|x] @ Wt^T + b), fused score ----------------
// Merged pass 1+2: (A_hi + A_lo) * W_hi with shared B fragments + prefetch pipeline.
__device__ __forceinline__ void gemm_pass12(uint32_t aHi, uint32_t aLo, uint32_t wBase,
                                            int wm, int wn, int lane, float cc[16][4]) {
    int arow = wm + (lane & 15);
    int acol = (lane >> 4) << 3;
    uint32_t ah = aHi + (uint32_t)arow * PITCHB + (uint32_t)acol * 2;
    uint32_t al = aLo + (uint32_t)arow * PITCHB + (uint32_t)acol * 2;
    int brow = (lane & 7) + ((lane >> 4) << 3);
    int bcol = ((lane >> 3) & 1) << 3;
    uint32_t bb = wBase + (uint32_t)(wn + brow) * PITCHB + (uint32_t)bcol * 2;

    uint32_t h0[4], h1[4], l0[4], l1[4], b[4][4];
    ldsm_x4(h0, ah);
    ldsm_x4(h1, ah + 16 * PITCHB);
    ldsm_x4(l0, al);
    ldsm_x4(l1, al + 16 * PITCHB);
    #pragma unroll
    for (int ng = 0; ng < 4; ng++) ldsm_x4(b[ng], bb + ng * 16 * PITCHB);

    #pragma unroll
    for (int ks = 0; ks < 16; ks++) {
        uint32_t nh0[4], nh1[4], nl0[4], nl1[4], nb[4][4];
        if (ks < 15) {
            uint32_t o = (uint32_t)(ks + 1) * 32;
            ldsm_x4(nh0, ah + o);
            ldsm_x4(nh1, ah + 16 * PITCHB + o);
            ldsm_x4(nl0, al + o);
            ldsm_x4(nl1, al + 16 * PITCHB + o);
            #pragma unroll
            for (int ng = 0; ng < 4; ng++) ldsm_x4(nb[ng], bb + ng * 16 * PITCHB + o);
        }
        #pragma unroll
        for (int nt = 0; nt < 8; nt++) {
            const uint32_t* bf = &b[nt >> 1][(nt & 1) * 2];
            mma_bf16(cc[nt],     h0, bf);
            mma_bf16(cc[8 + nt], h1, bf);
            mma_bf16(cc[nt],     l0, bf);
            mma_bf16(cc[8 + nt], l1, bf);
        }
        if (ks < 15) {
            #pragma unroll
            for (int q = 0; q < 4; q++) {
                h0[q] = nh0[q]; h1[q] = nh1[q]; l0[q] = nl0[q]; l1[q] = nl1[q];
                #pragma unroll
                for (int ng = 0; ng < 4; ng++) b[ng][q] = nb[ng][q];
            }
        }
    }
}

// Pass 3: A_hi * W_lo with prefetch pipeline.
__device__ __forceinline__ void gemm_pass3(uint32_t aHi, uint32_t wBase,
                                           int wm, int wn, int lane, float cc[16][4]) {
    int arow = wm + (lane & 15);
    int acol = (lane >> 4) << 3;
    uint32_t ah = aHi + (uint32_t)arow * PITCHB + (uint32_t)acol * 2;
    int brow = (lane & 7) + ((lane >> 4) << 3);
    int bcol = ((lane >> 3) & 1) << 3;
    uint32_t bb = wBase + (uint32_t)(wn + brow) * PITCHB + (uint32_t)bcol * 2;

    uint32_t h0[4], h1[4], b[4][4];
    ldsm_x4(h0, ah);
    ldsm_x4(h1, ah + 16 * PITCHB);
    #pragma unroll
    for (int ng = 0; ng < 4; ng++) ldsm_x4(b[ng], bb + ng * 16 * PITCHB);

    #pragma unroll
    for (int ks = 0; ks < 16; ks++) {
        uint32_t nh0[4], nh1[4], nb[4][4];
        if (ks < 15) {
            uint32_t o = (uint32_t)(ks + 1) * 32;
            ldsm_x4(nh0, ah + o);
            ldsm_x4(nh1, ah + 16 * PITCHB + o);
            #pragma unroll
            for (int ng = 0; ng < 4; ng++) ldsm_x4(nb[ng], bb + ng * 16 * PITCHB + o);
        }
        #pragma unroll
        for (int nt = 0; nt < 8; nt++) {
            const uint32_t* bf = &b[nt >> 1][(nt & 1) * 2];
            mma_bf16(cc[nt],     h0, bf);
            mma_bf16(cc[8 + nt], h1, bf);
        }
        if (ks < 15) {
            #pragma unroll
            for (int q = 0; q < 4; q++) {
                h0[q] = nh0[q]; h1[q] = nh1[q];
                #pragma unroll
                for (int ng = 0; ng < 4; ng++) b[ng][q] = nb[ng][q];
            }
        }
    }
}

__global__ void __launch_bounds__(256) k_gemm_tc(
    const float* __restrict__ A, const float* __restrict__ X,
    const __nv_bfloat16* __restrict__ wthi, const __nv_bfloat16* __restrict__ wtlo,
    const float* __restrict__ bias, const float* __restrict__ pw,
    float* __restrict__ out, float* __restrict__ score) {
    extern __shared__ char smem[];
    uint32_t sb = smem_to_u32(smem);
    int tid = threadIdx.x, wid = tid >> 5, lane = tid & 31;
    int r0 = blockIdx.x * 128;

    float* sbias = (float*)(smem + OFF_BIAS);
    float* spw   = (float*)(smem + OFF_PW);
    float* ssc   = (float*)(smem + OFF_SC);
    if (tid < 128) {
        sbias[tid] = bias[tid];
        spw[tid] = pw[tid];
        ssc[tid] = 0.f;
    }
    __syncthreads();
    if (tid == 0) {
        float s = 0.f;
        for (int i = 0; i < 128; i++) s += spw[i] * spw[i];
        *(float*)(smem + OFF_INV) = rsqrtf(s);
    }

    for (int c = tid; c < 4096; c += 256) {
        int row = c >> 5, col4 = (c & 31) << 2;
        float4 v = *(const float4*)(A + (size_t)(r0 + row) * 128 + col4);
        float4 u = *(const float4*)(X + (size_t)(r0 + row) * 128 + col4);
        #pragma unroll
        for (int half = 0; half < 2; half++) {
            float4 w = half ? u : v;
            __nv_bfloat16 hx = __float2bfloat16_rn(w.x), hy = __float2bfloat16_rn(w.y);
            __nv_bfloat16 hz = __float2bfloat16_rn(w.z), hw = __float2bfloat16_rn(w.w);
            __nv_bfloat16 lx = __float2bfloat16_rn(w.x - __bfloat162float(hx));
            __nv_bfloat16 ly = __float2bfloat16_rn(w.y - __bfloat162float(hy));
            __nv_bfloat16 lz = __float2bfloat16_rn(w.z - __bfloat162float(hz));
            __nv_bfloat16 lw = __float2bfloat16_rn(w.w - __bfloat162float(hw));
            __nv_bfloat162 h01 = __halves2bfloat162(hx, hy), h23 = __halves2bfloat162(hz, hw);
            __nv_bfloat162 l01 = __halves2bfloat162(lx, ly), l23 = __halves2bfloat162(lz, lw);
            uint32_t off = (uint32_t)row * PITCHB + (uint32_t)(half * 128 + col4) * 2;
            uint2 hv; hv.x = *(uint32_t*)&h01; hv.y = *(uint32_t*)&h23;
            uint2 lv; lv.x = *(uint32_t*)&l01; lv.y = *(uint32_t*)&l23;
            *(uint2*)(smem + OFF_AHI + off) = hv;
            *(uint2*)(smem + OFF_ALO + off) = lv;
        }
    }
    for (int c = tid; c < 4096; c += 256) {
        int n = c >> 5, k8 = (c & 31) << 3;
        uint4 raw = *(const uint4*)(wthi + (size_t)n * 256 + k8);
        *(uint4*)(smem + OFF_W + (uint32_t)n * PITCHB + (uint32_t)k8 * 2) = raw;
    }
    __syncthreads();

    int wm = (wid & 3) * 32, wn = (wid >> 2) * 64;
    float cc[16][4];
    #pragma unroll
    for (int i = 0; i < 16; i++)
        #pragma unroll
        for (int j = 0; j < 4; j++) cc[i][j] = 0.f;

    gemm_pass12(sb + OFF_AHI, sb + OFF_ALO, sb + OFF_W, wm, wn, lane, cc);  // (A_hi+A_lo)*W_hi
    __syncthreads();
    for (int c = tid; c < 4096; c += 256) {                                 // swap in W_lo
        int n = c >> 5, k8 = (c & 31) << 3;
        uint4 raw = *(const uint4*)(wtlo + (size_t)n * 256 + k8);
        *(uint4*)(smem + OFF_W + (uint32_t)n * PITCHB + (uint32_t)k8 * 2) = raw;
    }
    __syncthreads();
    gemm_pass3(sb + OFF_AHI, sb + OFF_W, wm, wn, lane, cc);                 // A_hi*W_lo

    int g = lane >> 2, tig = lane & 3;
    float p[4] = {0.f, 0.f, 0.f, 0.f};
    #pragma unroll
    for (int mt = 0; mt < 2; mt++) {
        #pragma unroll
        for (int nt = 0; nt < 8; nt++) {
            float* cf = cc[mt * 8 + nt];
            int col0 = wn + nt * 8 + tig * 2;
            float pw0 = spw[col0], pw1 = spw[col0 + 1];
            float b0 = sbias[col0], b1 = sbias[col0 + 1];
            float o0 = fmaxf(cf[0] + b0, 0.f), o1 = fmaxf(cf[1] + b1, 0.f);
            float o2 = fmaxf(cf[2] + b0, 0.f), o3 = fmaxf(cf[3] + b1, 0.f);
            int rowA = r0 + wm + mt * 16 + g;
            float2 s0; s0.x = o0; s0.y = o1;
            float2 s1; s1.x = o2; s1.y = o3;
            *(float2*)(out + (size_t)rowA * 128 + col0) = s0;
            *(float2*)(out + (size_t)(rowA + 8) * 128 + col0) = s1;
            p[mt * 2 + 0] += o0 * pw0 + o1 * pw1;
            p[mt * 2 + 1] += o2 * pw0 + o3 * pw1;
        }
    }
    #pragma unroll
    for (int off = 1; off <= 2; off <<= 1) {
        #pragma unroll
        for (int i = 0; i < 4; i++) p[i] += __shfl_xor_sync(0xffffffffu, p[i], off);
    }
    if (tig == 0) {
        atomicAdd(&ssc[wm + g], p[0]);
        atomicAdd(&ssc[wm + 8 + g], p[1]);
        atomicAdd(&ssc[wm + 16 + g], p[2]);
        atomicAdd(&ssc[wm + 24 + g], p[3]);
    }
    __syncthreads();
    if (tid < 128) {
        float invn = *(const float*)(smem + OFF_INV);
        score[r0 + tid] = tanhf(ssc[tid] * invn);
    }
}

// ---------------- per-graph top-k pool + fused readout ----------------
__global__ void k_pool(const float* __restrict__ h, const float* __restrict__ score,
                       float* __restrict__ hout, int* __restrict__ kept,
                       int* __restrict__ newidx, float* __restrict__ z,
                       int n_per, int k) {
    __shared__ unsigned long long s_key[2048];
    __shared__ float red[32][128];
    int g = blockIdx.x;
    int tid = threadIdx.x;
    int bd = blockDim.x;
    int base = g * n_per;
    for (int i = tid; i < n_per; i += bd) {
        float s = score[base + i];
        unsigned u = __float_as_uint(s);
        unsigned au = (u & 0x80000000u) ? ~u : (u | 0x80000000u);
        unsigned du = ~au;
        s_key[i] = ((unsigned long long)du << 32) | (unsigned)i;
        kept[base + i] = 0;
    }
    for (int size = 2; size <= n_per; size <<= 1) {
        for (int stride = size >> 1; stride > 0; stride >>= 1) {
            __syncthreads();
            int half = n_per >> 1;
            for (int t = tid; t < half; t += bd) {
                int i = 2 * t - (t & (stride - 1));
                int j = i + stride;
                unsigned long long a = s_key[i], c = s_key[j];
                bool up = ((i & size) == 0);
                if ((a > c) == up) { s_key[i] = c; s_key[j] = a; }
            }
        }
    }
    __syncthreads();
    for (int t = tid; t < k; t += bd) {
        int li = (int)(s_key[t] & 0xffffffffull);
        kept[base + li] = 1;
        newidx[base + li] = g * k + t;
    }
    // gather + gate + accumulate per-graph max/sum (fused readout)
    int w = tid >> 5, lane = tid & 31;
    float mx0 = -FLT_MAX, mx1 = -FLT_MAX, mx2 = -FLT_MAX, mx3 = -FLT_MAX;
    float sm0 = 0.f, sm1 = 0.f, sm2 = 0.f, sm3 = 0.f;
    for (int t = w; t < k; t += 32) {
        int li = (int)(s_key[t] & 0xffffffffull);
        int v = base + li;
        float sc = score[v];
        float4 val = *(const float4*)(h + (size_t)v * NF + lane * 4);
        float4 o; o.x = val.x * sc; o.y = val.y * sc; o.z = val.z * sc; o.w = val.w * sc;
        *(float4*)(hout + (size_t)(g * k + t) * NF + lane * 4) = o;
        mx0 = fmaxf(mx0, o.x); mx1 = fmaxf(mx1, o.y);
        mx2 = fmaxf(mx2, o.z); mx3 = fmaxf(mx3, o.w);
        sm0 += o.x; sm1 += o.y; sm2 += o.z; sm3 += o.w;
    }
    red[w][lane * 4 + 0] = mx0; red[w][lane * 4 + 1] = mx1;
    red[w][lane * 4 + 2] = mx2; red[w][lane * 4 + 3] = mx3;
    __syncthreads();
    if (tid < 128) {
        float m = red[0][tid];
        #pragma unroll
        for (int j = 1; j < 32; j++) m = fmaxf(m, red[j][tid]);
        z[g * 256 + tid] += m;
    }
    __syncthreads();
    red[w][lane * 4 + 0] = sm0; red[w][lane * 4 + 1] = sm1;
    red[w][lane * 4 + 2] = sm2; red[w][lane * 4 + 3] = sm3;
    __syncthreads();
    if (tid < 128) {
        float s = 0.f;
        #pragma unroll
        for (int j = 0; j < 32; j++) s += red[j][tid];
        z[g * 256 + 128 + tid] += s / (float)k;
    }
}

// ---------------- fused edge-compact + adjacency build (atomic-free) ----------------
__global__ void k_compact_slot(const int* __restrict__ oslot, const int* __restrict__ odeg,
                               const int* __restrict__ kept, const int* __restrict__ newidx,
                               int* __restrict__ nslot, int* __restrict__ ndeg, int n_old) {
    int node = blockIdx.x * 8 + (threadIdx.x >> 5);
    if (node >= n_old) return;
    int lane = threadIdx.x & 31;
    if (!kept[node]) return;                  // warp-uniform
    int nid = newidx[node];
    int d = odeg[node];
    const int* row = oslot + (size_t)node * CAP;
    int* nrow = nslot + (size_t)nid * CAP;
    int total = 0;
    #pragma unroll
    for (int half = 0; half < CAP; half += 32) {
        int j = half + lane;
        bool keep = false;
        int ns = 0;
        if (j < d) {
            int s = row[j];
            if (kept[s]) { keep = true; ns = newidx[s]; }
        }
        unsigned m = __ballot_sync(0xffffffffu, keep);
        if (keep) nrow[total + __popc(m & ((1u << lane) - 1u))] = ns;
        total += __popc(m);
        if (d <= half + 32) break;
    }
    if (lane == 0) ndeg[nid] = total;
}

// ---------------- final MLP + log_softmax ----------------
__global__ void k_mlp(const float* __restrict__ z,
                      const float* __restrict__ w1, const float* __restrict__ b1,
                      const float* __restrict__ w2, const float* __restrict__ b2,
                      const float* __restrict__ w3, const float* __restrict__ b3,
                      float* __restrict__ out) {
    __shared__ float zin[256];
    __shared__ float h1[128];
    __shared__ float h2[64];
    __shared__ float z2[2];
    int g = blockIdx.x, tid = threadIdx.x;
    zin[tid] = z[g * 256 + tid];
    zin[tid + 128] = z[g * 256 + 128 + tid];
    __syncthreads();
    float a = b1[tid];
    for (int k2 = 0; k2 < 256; k2++) a += zin[k2] * w1[k2 * 128 + tid];
    h1[tid] = fmaxf(a, 0.f);
    __syncthreads();
    if (tid < 64) {
        float a2 = b2[tid];
        for (int k2 = 0; k2 < 128; k2++) a2 += h1[k2] * w2[k2 * 64 + tid];
        h2[tid] = fmaxf(a2, 0.f);
    }
    __syncthreads();
    if (tid < 2) {
        float a3 = b3[tid];
        for (int k2 = 0; k2 < 64; k2++) a3 += h2[k2] * w3[k2 * 2 + tid];
        z2[tid] = a3;
    }
    __syncthreads();
    if (tid < 2) {
        float m = fmaxf(z2[0], z2[1]);
        float lse = m + logf(expf(z2[0] - m) + expf(z2[1] - m));
        out[g * 2 + tid] = z2[tid] - lse;
    }
}

// ---------------- host ----------------
extern "C" void kernel_launch(void* const* d_in, const int* in_sizes, int n_in,
                              void* d_out, int out_size) {
    const float* x   = (const float*)d_in[0];
    const int*   src = (const int*)d_in[1];
    const int*   dst = (const int*)d_in[2];
    const float* w1l = (const float*)d_in[3];
    const float* b1  = (const float*)d_in[4];
    const float* w1r = (const float*)d_in[5];
    const float* pw1 = (const float*)d_in[6];
    const float* w2l = (const float*)d_in[7];
    const float* b2  = (const float*)d_in[8];
    const float* w2r = (const float*)d_in[9];
    const float* pw2 = (const float*)d_in[10];
    const float* w3l = (const float*)d_in[11];
    const float* b3  = (const float*)d_in[12];
    const float* w3r = (const float*)d_in[13];
    const float* pw3 = (const float*)d_in[14];
    const float* l1w = (const float*)d_in[15];
    const float* l1b = (const float*)d_in[16];
    const float* l2w = (const float*)d_in[17];
    const float* l2b = (const float*)d_in[18];
    const float* l3w = (const float*)d_in[19];
    const float* l3b = (const float*)d_in[20];
    float* out = (float*)d_out;

    float *p_h, *p_h2, *p_mean, *p_score, *p_z;
    int *p_slotA, *p_slotB, *p_degA, *p_degB, *p_kept, *p_newidx;
    __nv_bfloat16 *p_wthi, *p_wtlo;
    cudaGetSymbolAddress((void**)&p_h, g_h);
    cudaGetSymbolAddress((void**)&p_h2, g_h2);
    cudaGetSymbolAddress((void**)&p_mean, g_mean);
    cudaGetSymbolAddress((void**)&p_score, g_score);
    cudaGetSymbolAddress((void**)&p_z, g_z);
    cudaGetSymbolAddress((void**)&p_slotA, g_slotA);
    cudaGetSymbolAddress((void**)&p_slotB, g_slotB);
    cudaGetSymbolAddress((void**)&p_degA, g_degA);
    cudaGetSymbolAddress((void**)&p_degB, g_degB);
    cudaGetSymbolAddress((void**)&p_kept, g_kept);
    cudaGetSymbolAddress((void**)&p_newidx, g_newidx);
    cudaGetSymbolAddress((void**)&p_wthi, g_wthi);
    cudaGetSymbolAddress((void**)&p_wtlo, g_wtlo);

    cudaFuncSetAttribute(k_gemm_tc, cudaFuncAttributeMaxDynamicSharedMemorySize, GSMEM);

    // ===== layer 1 (launch #4 = k_gemm_tc -> ncu sample) =====
    k_setup<<<512, 256>>>(w1l, w1r, w2l, w2r, w3l, w3r, p_wthi, p_wtlo);
    k_slot1<<<EMAX / 256, 256>>>(src, dst, p_degA, p_slotA);
    k_aggregate<<<131072 / 8, 256>>>(x, p_slotA, p_degA, p_mean);
    k_gemm_tc<<<131072 / 128, 256, GSMEM>>>(p_mean, x, p_wthi, p_wtlo, b1, pw1, p_h2, p_score);
    k_pool<<<64, 1024>>>(p_h2, p_score, p_h, p_kept, p_newidx, p_z, 2048, 1024);
    k_compact_slot<<<131072 / 8, 256>>>(p_slotA, p_degA, p_kept, p_newidx,
                                        p_slotB, p_degB, 131072);

    // ===== layer 2 =====
    k_aggregate<<<65536 / 8, 256>>>(p_h, p_slotB, p_degB, p_mean);
    k_gemm_tc<<<65536 / 128, 256, GSMEM>>>(p_mean, p_h, p_wthi + 32768, p_wtlo + 32768, b2, pw2, p_h2, p_score);
    k_pool<<<64, 1024>>>(p_h2, p_score, p_h, p_kept, p_newidx, p_z, 1024, 512);
    k_compact_slot<<<65536 / 8, 256>>>(p_slotB, p_degB, p_kept, p_newidx,
                                       p_slotA, p_degA, 65536);

    // ===== layer 3 =====
    k_aggregate<<<32768 / 8, 256>>>(p_h, p_slotA, p_degA, p_mean);
    k_gemm_tc<<<32768 / 128, 256, GSMEM>>>(p_mean, p_h, p_wthi + 65536, p_wtlo + 65536, b3, pw3, p_h2, p_score);
    k_pool<<<64, 1024>>>(p_h2, p_score, p_h, p_kept, p_newidx, p_z, 512, 256);

    // ===== head =====
    k_mlp<<<64, 128>>>(p_z, l1w, l1b, l2w, l2b, l3w, l3b, out);
}